// round 10
// baseline (speedup 1.0000x reference)
#include <cuda_runtime.h>
#include <cstdint>

// ---------------------------------------------------------------------------
// QFCModel analytic collapse, round 4: 8 lanes per image (R3 load scheme)
// with the k_bn grid-size bug fixed (must cover all B float4 outputs).
//
//   theta_i = mean of pixels p in [0,144) with (p%24)/6 == i
//   e_i     = cos(beta_i)*cos(theta_i) + sin(alpha_i)*sin(beta_i)*sin(theta_i)
//   out     = [e0, e0*e1, e0*e1*e2, e0*e1*e2*e3], then BatchNorm1d (train).
//
// float4 index f = 8t + r (t=0..4, lane r=0..7; t=4 only r<4).
// class c = f mod 6 -> quadrants:
//   0: all->q0   1: xy->q0, zw->q1   2: all->q1
//   3: all->q2   4: xy->q2, zw->q3   5: all->q3
// ---------------------------------------------------------------------------

#define BLK 512
#define MAX_NBLK 2048

__device__ double g_partial[8][MAX_NBLK];  // [0..3]=sum(q), [4..7]=sumsq(q)
__device__ float  g_scale[4];
__device__ float  g_shift[4];

__global__ __launch_bounds__(BLK)
void k_circuit(const float* __restrict__ x,
               const float* __restrict__ params,
               float* __restrict__ raw)
{
    const int t    = blockIdx.x * BLK + threadIdx.x;   // 8*B threads total
    const int b    = t >> 3;                            // image
    const int r    = t & 7;                             // sub-lane within group
    const int lane = threadIdx.x & 31;

    const float4* xv = reinterpret_cast<const float4*>(x) + (size_t)b * 144 + r;

    // 4 full loads + predicated tail: group covers 128B contiguous per load
    float4 v[5];
    #pragma unroll
    for (int tt = 0; tt < 4; ++tt) v[tt] = __ldg(xv + 8 * tt);
    if (r < 4) v[4] = __ldg(xv + 32);
    else       v[4] = make_float4(0.f, 0.f, 0.f, 0.f);

    float q0 = 0.f, q1 = 0.f, q2 = 0.f, q3 = 0.f;
    #pragma unroll
    for (int tt = 0; tt < 5; ++tt) {
        const int c = (8 * tt + r) % 6;       // runtime class, uniform math
        const float xy  = v[tt].x + v[tt].y;
        const float zw  = v[tt].z + v[tt].w;
        const float all = xy + zw;
        q0 += (c == 0) ? all : ((c == 1) ? xy : 0.f);
        q1 += (c == 2) ? all : ((c == 1) ? zw : 0.f);
        q2 += (c == 3) ? all : ((c == 4) ? xy : 0.f);
        q3 += (c == 5) ? all : ((c == 4) ? zw : 0.f);
    }

    // reduce across the 8 lanes of the group
    #pragma unroll
    for (int off = 1; off <= 4; off <<= 1) {
        q0 += __shfl_xor_sync(0xffffffffu, q0, off);
        q1 += __shfl_xor_sync(0xffffffffu, q1, off);
        q2 += __shfl_xor_sync(0xffffffffu, q2, off);
        q3 += __shfl_xor_sync(0xffffffffu, q3, off);
    }

    // lane (r&3) handles quadrant (r&3); lanes 4-7 mirror 0-3 (harmless)
    const int rr = r & 3;
    const float sA = (rr & 2) ? q2 : q0;
    const float sB = (rr & 2) ? q3 : q1;
    const float sr = (rr & 1) ? sB : sA;

    const float alpha = __ldg(params + 2 * rr);
    const float beta  = __ldg(params + 2 * rr + 1);
    float sb, cb;  sincosf(beta, &sb, &cb);
    const float sa = sinf(alpha);
    const float th = sr * (1.0f / 36.0f);
    float st, ct;  sincosf(th, &st, &ct);
    const float e = cb * ct + sa * sb * st;

    // cumulative product across the group
    const int gbase = lane & ~7;
    const float e0 = __shfl_sync(0xffffffffu, e, gbase + 0);
    const float e1 = __shfl_sync(0xffffffffu, e, gbase + 1);
    const float e2 = __shfl_sync(0xffffffffu, e, gbase + 2);
    const float e3 = __shfl_sync(0xffffffffu, e, gbase + 3);
    float o = e0;
    o *= (rr >= 1) ? e1 : 1.f;
    o *= (rr >= 2) ? e2 : 1.f;
    o *= (rr >= 3) ? e3 : 1.f;

    if (r < 4) raw[(b << 2) | rr] = o;   // 16 consecutive floats per warp

    // ---- deterministic BN partials (double) ----
    // active quantity lanes: (lane&7) < 4; quantity index = lane&3
    double od = (r < 4) ? (double)o : 0.0;
    double oq = od * od;
    // sum across the 4 images held by this warp (lanes l, l^8, l^16, l^24)
    #pragma unroll
    for (int off = 8; off <= 16; off <<= 1) {
        od += __shfl_xor_sync(0xffffffffu, od, off);
        oq += __shfl_xor_sync(0xffffffffu, oq, off);
    }

    __shared__ double sw[BLK / 32][4][2];
    const int warp = threadIdx.x >> 5;
    if (lane < 4) { sw[warp][lane][0] = od; sw[warp][lane][1] = oq; }
    __syncthreads();

    if (threadIdx.x < 8) {
        const int q     = threadIdx.x & 3;
        const int which = threadIdx.x >> 2;
        double tsum = 0.0;
        #pragma unroll
        for (int w = 0; w < BLK / 32; ++w) tsum += sw[w][q][which];
        g_partial[threadIdx.x][blockIdx.x] = tsum;   // [0..3]=sum, [4..7]=sumsq
    }
}

__global__ void k_stats(const float* __restrict__ gamma,
                        const float* __restrict__ beta,
                        int nblk, double inv_batch)
{
    __shared__ double tot[8];
    const int warp = threadIdx.x >> 5;
    const int lane = threadIdx.x & 31;

    if (warp < 8) {
        double v = 0.0;
        for (int i = lane; i < nblk; i += 32) v += g_partial[warp][i];
        #pragma unroll
        for (int off = 16; off > 0; off >>= 1)
            v += __shfl_xor_sync(0xffffffffu, v, off);
        if (lane == 0) tot[warp] = v;
    }
    __syncthreads();

    if (threadIdx.x < 4) {
        const int i = threadIdx.x;
        const double mean = tot[i] * inv_batch;
        const double var  = tot[i + 4] * inv_batch - mean * mean;
        const float invstd = rsqrtf((float)var + 1e-5f);
        const float sc = __ldg(gamma + i) * invstd;
        g_scale[i] = sc;
        g_shift[i] = __ldg(beta + i) - (float)mean * sc;
    }
}

__global__ __launch_bounds__(256)
void k_bn(float* __restrict__ out)
{
    const int b = blockIdx.x * 256 + threadIdx.x;   // one float4 per thread
    float4 v = reinterpret_cast<float4*>(out)[b];
    v.x = v.x * g_scale[0] + g_shift[0];
    v.y = v.y * g_scale[1] + g_shift[1];
    v.z = v.z * g_scale[2] + g_shift[2];
    v.w = v.w * g_scale[3] + g_shift[3];
    reinterpret_cast<float4*>(out)[b] = v;
}

extern "C" void kernel_launch(void* const* d_in, const int* in_sizes, int n_in,
                              void* d_out, int out_size)
{
    const float* x      = (const float*)d_in[0];   // [B,1,24,24]
    const float* params = (const float*)d_in[1];   // [4,2]
    const float* gamma  = (const float*)d_in[2];   // [4]
    const float* beta   = (const float*)d_in[3];   // [4]
    float* out = (float*)d_out;                    // [B,4] float32

    const int B    = in_sizes[0] / 576;            // 65536
    const int nblk = (8 * B) / BLK;                // 1024 (64 images / block)

    k_circuit<<<nblk, BLK>>>(x, params, out);
    k_stats<<<1, 256>>>(gamma, beta, nblk, 1.0 / (double)B);
    k_bn<<<B / 256, 256>>>(out);                   // FIX: B float4 outputs
}

// round 15
// speedup vs baseline: 1.5424x; 1.5424x over previous
#include <cuda_runtime.h>
#include <cstdint>

// ---------------------------------------------------------------------------
// QFCModel analytic collapse, round 5.
// Back to the measured-best R2 pattern (4 lanes/image, compile-time quadrant
// classes) + 2-iteration grid-stride loop (warp desync for latency hiding)
// + all-float BN partial tail (no DADD/64-bit-shfl latency chains).
//
//   theta_i = mean of pixels p in [0,144) with (p%24)/6 == i
//   e_i     = cos(beta_i)*cos(theta_i) + sin(alpha_i)*sin(beta_i)*sin(theta_i)
//   out     = [e0, e0*e1, e0*e1*e2, e0*e1*e2*e3], then BatchNorm1d (train).
// ---------------------------------------------------------------------------

#define BLK   256
#define GRID  512          // 131072 threads, 2 images per 4-lane group
#define MAX_NBLK 2048

__device__ float g_partial[8][MAX_NBLK];   // [0..3]=sum(q), [4..7]=sumsq(q)
__device__ float g_scale[4];
__device__ float g_shift[4];

__global__ __launch_bounds__(BLK)
void k_circuit(const float* __restrict__ x,
               const float* __restrict__ params,
               float* __restrict__ raw,
               int group_stride)            // images per iteration
{
    const int t    = blockIdx.x * BLK + threadIdx.x;
    const int g    = t >> 2;                 // group index (image for iter 0)
    const int r    = t & 3;                  // sub-lane within group
    const int lane = threadIdx.x & 31;

    // quadrant-constant trig (params are uniform): hoisted out of the loop
    const float alpha = __ldg(params + 2 * r);
    const float beta  = __ldg(params + 2 * r + 1);
    float sb, cb;  sincosf(beta, &sb, &cb);
    const float sasb = sinf(alpha) * sb;

    float acc_s = 0.f, acc_q = 0.f;          // per-thread BN partials (float)

    #pragma unroll
    for (int iter = 0; iter < 2; ++iter) {
        const int b = g + iter * group_stride;
        const float4* xv = reinterpret_cast<const float4*>(x) + (size_t)b * 144 + r;

        // front-batched loads: 64B contiguous per 4-lane group per access
        float4 v[9];
        #pragma unroll
        for (int tt = 0; tt < 9; ++tt) v[tt] = __ldg(xv + 4 * tt);

        // phase accumulators: phase j = tt mod 3 has constant class (4j+r) mod 6
        float xy0 = 0.f, xy1 = 0.f, xy2 = 0.f;
        float zw0 = 0.f, zw1 = 0.f, zw2 = 0.f;
        #pragma unroll
        for (int tt = 0; tt < 9; ++tt) {
            const float a = v[tt].x + v[tt].y;
            const float c = v[tt].z + v[tt].w;
            if (tt % 3 == 0)      { xy0 += a; zw0 += c; }
            else if (tt % 3 == 1) { xy1 += a; zw1 += c; }
            else                  { xy2 += a; zw2 += c; }
        }

        // scatter phases into quadrant sums (classes compile-time per r)
        float s0 = 0.f, s1 = 0.f, s2 = 0.f, s3 = 0.f;
        switch (r) {
        case 0:  s0 = xy0 + zw0; s2 = xy1; s3 = zw1; s1 = xy2 + zw2; break;
        case 1:  s0 = xy0; s1 = zw0; s3 = xy1 + zw1; s2 = xy2 + zw2; break;
        case 2:  s1 = xy0 + zw0; s0 = xy1 + zw1; s2 = xy2; s3 = zw2; break;
        default: s2 = xy0 + zw0; s0 = xy1; s1 = zw1; s3 = xy2 + zw2; break;
        }

        // reduce across the 4 lanes of the group
        #pragma unroll
        for (int off = 1; off <= 2; off <<= 1) {
            s0 += __shfl_xor_sync(0xffffffffu, s0, off);
            s1 += __shfl_xor_sync(0xffffffffu, s1, off);
            s2 += __shfl_xor_sync(0xffffffffu, s2, off);
            s3 += __shfl_xor_sync(0xffffffffu, s3, off);
        }

        // lane r handles quadrant r
        const float sA = (r & 2) ? s2 : s0;
        const float sB = (r & 2) ? s3 : s1;
        const float sr = (r & 1) ? sB : sA;

        const float th = sr * (1.0f / 36.0f);
        float st, ct;  sincosf(th, &st, &ct);
        const float e = cb * ct + sasb * st;

        // cumulative product across the group
        const int gbase = lane & ~3;
        const float e0 = __shfl_sync(0xffffffffu, e, gbase + 0);
        const float e1 = __shfl_sync(0xffffffffu, e, gbase + 1);
        const float e2 = __shfl_sync(0xffffffffu, e, gbase + 2);
        const float e3 = __shfl_sync(0xffffffffu, e, gbase + 3);
        float o = e0;
        o *= (r >= 1) ? e1 : 1.f;
        o *= (r >= 2) ? e2 : 1.f;
        o *= (r >= 3) ? e3 : 1.f;

        raw[(b << 2) | r] = o;               // coalesced: 128B per warp

        acc_s += o;
        acc_q += o * o;
    }

    // ---- warp reduce: lanes with equal (lane&3) hold the same quantity ----
    #pragma unroll
    for (int off = 4; off <= 16; off <<= 1) {
        acc_s += __shfl_xor_sync(0xffffffffu, acc_s, off);
        acc_q += __shfl_xor_sync(0xffffffffu, acc_q, off);
    }

    __shared__ float sw[BLK / 32][4][2];
    const int warp = threadIdx.x >> 5;
    if (lane < 4) { sw[warp][lane][0] = acc_s; sw[warp][lane][1] = acc_q; }
    __syncthreads();

    if (threadIdx.x < 8) {
        const int q     = threadIdx.x & 3;
        const int which = threadIdx.x >> 2;
        float tsum = 0.f;
        #pragma unroll
        for (int w = 0; w < BLK / 32; ++w) tsum += sw[w][q][which];
        g_partial[threadIdx.x][blockIdx.x] = tsum;   // [0..3]=sum, [4..7]=sumsq
    }
}

__global__ void k_stats(const float* __restrict__ gamma,
                        const float* __restrict__ beta,
                        int nblk, double inv_batch)
{
    __shared__ double tot[8];
    const int warp = threadIdx.x >> 5;
    const int lane = threadIdx.x & 31;

    if (warp < 8) {
        double v = 0.0;
        for (int i = lane; i < nblk; i += 32) v += (double)g_partial[warp][i];
        #pragma unroll
        for (int off = 16; off > 0; off >>= 1)
            v += __shfl_xor_sync(0xffffffffu, v, off);
        if (lane == 0) tot[warp] = v;
    }
    __syncthreads();

    if (threadIdx.x < 4) {
        const int i = threadIdx.x;
        const double mean = tot[i] * inv_batch;
        const double var  = tot[i + 4] * inv_batch - mean * mean;
        const float invstd = rsqrtf((float)var + 1e-5f);
        const float sc = __ldg(gamma + i) * invstd;
        g_scale[i] = sc;
        g_shift[i] = __ldg(beta + i) - (float)mean * sc;
    }
}

__global__ __launch_bounds__(256)
void k_bn(float* __restrict__ out)
{
    const int b = blockIdx.x * 256 + threadIdx.x;   // one float4 per thread
    float4 v = reinterpret_cast<float4*>(out)[b];
    v.x = v.x * g_scale[0] + g_shift[0];
    v.y = v.y * g_scale[1] + g_shift[1];
    v.z = v.z * g_scale[2] + g_shift[2];
    v.w = v.w * g_scale[3] + g_shift[3];
    reinterpret_cast<float4*>(out)[b] = v;
}

extern "C" void kernel_launch(void* const* d_in, const int* in_sizes, int n_in,
                              void* d_out, int out_size)
{
    const float* x      = (const float*)d_in[0];   // [B,1,24,24]
    const float* params = (const float*)d_in[1];   // [4,2]
    const float* gamma  = (const float*)d_in[2];   // [4]
    const float* beta   = (const float*)d_in[3];   // [4]
    float* out = (float*)d_out;                    // [B,4] float32

    const int B = in_sizes[0] / 576;               // 65536
    const int group_stride = B / 2;                // 32768 images per iteration

    k_circuit<<<GRID, BLK>>>(x, params, out, group_stride);
    k_stats<<<1, 256>>>(gamma, beta, GRID, 1.0 / (double)B);
    k_bn<<<B / 256, 256>>>(out);
}